// round 2
// baseline (speedup 1.0000x reference)
#include <cuda_runtime.h>
#include <math.h>

#define C 16
#define DIM 16
#define LL 6
#define PTS 16
#define THREADS (PTS * C)

__device__ float g_Linv[C][DIM][DIM];
__device__ float g_hld[C];
__device__ int   g_identity;

__global__ void chol_prep_kernel(const float* __restrict__ cov) {
    int c = threadIdx.x;
    bool is_id = true;
    float A[DIM][DIM];
    for (int i = 0; i < DIM; i++)
        for (int j = 0; j < DIM; j++) {
            float v = cov[c * DIM * DIM + i * DIM + j];
            A[i][j] = v;
            if (v != (i == j ? 1.0f : 0.0f)) is_id = false;
        }
    for (int j = 0; j < DIM; j++) {
        float s = A[j][j];
        for (int k = 0; k < j; k++) s -= A[j][k] * A[j][k];
        float d = sqrtf(s);
        A[j][j] = d;
        float inv = 1.0f / d;
        for (int i = j + 1; i < DIM; i++) {
            float t = A[i][j];
            for (int k = 0; k < j; k++) t -= A[i][k] * A[j][k];
            A[i][j] = t * inv;
        }
    }
    float hld = 0.0f;
    for (int j = 0; j < DIM; j++) hld += logf(A[j][j]);
    float Li[DIM][DIM];
    for (int i = 0; i < DIM; i++)
        for (int j = 0; j < DIM; j++) Li[i][j] = 0.0f;
    for (int j = 0; j < DIM; j++) {
        Li[j][j] = 1.0f / A[j][j];
        for (int i = j + 1; i < DIM; i++) {
            float s = 0.0f;
            for (int k = j; k < i; k++) s += A[i][k] * Li[k][j];
            Li[i][j] = -s / A[i][i];
        }
    }
    for (int i = 0; i < DIM; i++)
        for (int j = 0; j < DIM; j++)
            g_Linv[c][i][j] = Li[i][j];
    g_hld[c] = hld;

    unsigned bits = __ballot_sync(0xFFFFu, is_id);
    if (c == 0) g_identity = (bits == 0xFFFFu) ? 1 : 0;
}

__global__ void __launch_bounds__(THREADS)
density_kernel(const float* __restrict__ z,
               const float* __restrict__ z0,
               const float* __restrict__ log_alpha,
               const float* __restrict__ beta,
               const float* __restrict__ mean,
               float* __restrict__ out,
               int N) {
    __shared__ float s_z0[LL][DIM][C];
    __shared__ float s_alpha[LL][C];
    __shared__ float s_beta[LL][C];
    __shared__ float s_mean[DIM][C];
    __shared__ float s_Linv[DIM * DIM][C];
    __shared__ float s_hld[C];
    __shared__ float s_z[PTS][DIM];
    __shared__ int   s_identity;

    const int tid = threadIdx.x;

    if (tid == 0) s_identity = g_identity;

    for (int i = tid; i < LL * C * DIM; i += THREADS) {
        int l = i / (C * DIM);
        int rem = i - l * C * DIM;
        int cc = rem / DIM;
        int d = rem - cc * DIM;
        s_z0[l][d][cc] = z0[i];
    }
    for (int i = tid; i < LL * C; i += THREADS) {
        int l = i / C, cc = i - l * C;
        s_alpha[l][cc] = __expf(log_alpha[i]);
        s_beta[l][cc]  = beta[i];
    }
    for (int i = tid; i < C * DIM; i += THREADS) {
        int cc = i / DIM, d = i - cc * DIM;
        s_mean[d][cc] = mean[i];
    }
    for (int i = tid; i < C * DIM * DIM; i += THREADS) {
        int cc = i / (DIM * DIM);
        int ij = i - cc * DIM * DIM;
        s_Linv[ij][cc] = ((const float*)g_Linv)[i];
    }
    if (tid < C) s_hld[tid] = g_hld[tid];

    {
        size_t base = (size_t)blockIdx.x * PTS * DIM;
        size_t idx = base + tid;
        s_z[0][tid] = (idx < (size_t)N * DIM) ? z[idx] : 0.0f;
    }
    __syncthreads();

    const int pt = tid >> 4;
    const int c  = tid & 15;
    const int n  = blockIdx.x * PTS + pt;
    if (n >= N) return;

    const int identity = s_identity;

    float zc[DIM];
    #pragma unroll
    for (int d = 0; d < DIM; d++) zc[d] = s_z[pt][d];

    float p1 = 1.0f, p2 = 1.0f;
    #pragma unroll
    for (int l = 0; l < LL; l++) {
        float zs[DIM];
        float r2 = 0.0f;
        #pragma unroll
        for (int d = 0; d < DIM; d++) {
            float v = zc[d] - s_z0[l][d][c];
            zs[d] = v;
            r2 = fmaf(v, v, r2);
        }
        float r = (r2 > 0.0f) ? r2 * rsqrtf(r2) : 0.0f;
        float alpha = s_alpha[l][c];
        float bet   = s_beta[l][c];
        float h  = __fdividef(1.0f, alpha + r);
        float bh = bet * h;
        float ah = alpha * h;
        #pragma unroll
        for (int d = 0; d < DIM; d++) zc[d] = fmaf(bh, zs[d], zc[d]);
        p1 = fmaf(p1, bh, p1);        // *= (1 + bh)
        p2 = fmaf(p2, bh * ah, p2);   // *= (1 + bh*ah), bh*ah == bh - b*r*h^2
    }
    float slj = 15.0f * __logf(p1) + __logf(p2);

    float diff[DIM];
    #pragma unroll
    for (int d = 0; d < DIM; d++) diff[d] = zc[d] - s_mean[d][c];

    float q = 0.0f;
    if (identity) {
        #pragma unroll
        for (int d = 0; d < DIM; d++) q = fmaf(diff[d], diff[d], q);
    } else {
        #pragma unroll
        for (int i = 0; i < DIM; i++) {
            float s = 0.0f;
            #pragma unroll
            for (int j = 0; j <= i; j++)
                s = fmaf(s_Linv[i * DIM + j][c], diff[j], s);
            q = fmaf(s, s, q);
        }
    }

    const float NEG_HALF_DIM_LOG2PI = -0.5f * 16.0f * 1.8378770664093453f;
    float lp = NEG_HALF_DIM_LOG2PI - 0.5f * q - s_hld[c] + slj;
    lp = isnan(lp) ? -INFINITY : lp;

    out[(size_t)n * C + c] = lp;
}

extern "C" void kernel_launch(void* const* d_in, const int* in_sizes, int n_in,
                              void* d_out, int out_size) {
    const float* z         = (const float*)d_in[0];
    const float* z0        = (const float*)d_in[1];
    const float* log_alpha = (const float*)d_in[2];
    const float* beta      = (const float*)d_in[3];
    const float* mean      = (const float*)d_in[4];
    const float* cov       = (const float*)d_in[5];
    float* out = (float*)d_out;

    const int N = in_sizes[0] / DIM;

    chol_prep_kernel<<<1, C>>>(cov);

    const int blocks = (N + PTS - 1) / PTS;
    density_kernel<<<blocks, THREADS>>>(z, z0, log_alpha, beta, mean, out, N);
}

// round 4
// speedup vs baseline: 2.8252x; 2.8252x over previous
#include <cuda_runtime.h>
#include <math.h>

#define C 16
#define DIM 16
#define LL 6
#define PPT 4                 // points per thread
#define GRP 16                // thread groups per block (tid>>4)
#define PTSB (GRP * PPT)      // 64 points per block
#define THREADS 256

__device__ float g_Linv[C][DIM][DIM];
__device__ float g_hld[C];
__device__ int   g_identity;

// ---------------------------------------------------------------------------
// Prep: parallel identity check; full Cholesky + triangular inverse only if
// cov != I. 256 threads.
// ---------------------------------------------------------------------------
__global__ void chol_prep_kernel(const float* __restrict__ cov) {
    const int tid = threadIdx.x;
    bool bad = false;
    for (int i = tid; i < C * DIM * DIM; i += THREADS) {
        int ij = i & 255;
        int r = ij >> 4, col = ij & 15;
        float v = cov[i];
        if (v != (r == col ? 1.0f : 0.0f)) bad = true;
    }
    int any_bad = __syncthreads_or((int)bad);

    if (!any_bad) {
        if (tid == 0) g_identity = 1;
        if (tid < C) g_hld[tid] = 0.0f;
        return;
    }

    if (tid == 0) g_identity = 0;
    if (tid >= C) return;
    int c = tid;
    float A[DIM][DIM];
    for (int i = 0; i < DIM; i++)
        for (int j = 0; j < DIM; j++)
            A[i][j] = cov[c * DIM * DIM + i * DIM + j];
    for (int j = 0; j < DIM; j++) {
        float s = A[j][j];
        for (int k = 0; k < j; k++) s -= A[j][k] * A[j][k];
        float d = sqrtf(s);
        A[j][j] = d;
        float inv = 1.0f / d;
        for (int i = j + 1; i < DIM; i++) {
            float t = A[i][j];
            for (int k = 0; k < j; k++) t -= A[i][k] * A[j][k];
            A[i][j] = t * inv;
        }
    }
    float hld = 0.0f;
    for (int j = 0; j < DIM; j++) hld += logf(A[j][j]);
    float Li[DIM][DIM];
    for (int i = 0; i < DIM; i++)
        for (int j = 0; j < DIM; j++) Li[i][j] = 0.0f;
    for (int j = 0; j < DIM; j++) {
        Li[j][j] = 1.0f / A[j][j];
        for (int i = j + 1; i < DIM; i++) {
            float s = 0.0f;
            for (int k = j; k < i; k++) s += A[i][k] * Li[k][j];
            Li[i][j] = -s / A[i][i];
        }
    }
    for (int i = 0; i < DIM; i++)
        for (int j = 0; j < DIM; j++)
            g_Linv[c][i][j] = Li[i][j];
    g_hld[c] = hld;
}

// ---------------------------------------------------------------------------
// Main: thread = (component c = tid&15, group g = tid>>4), handles 4 points
// n = base + g + 16*k. Parameter LDS amortized over 4 points; 4-way ILP.
// __launch_bounds__(256, 2): 128-reg ceiling, 2 CTAs/SM guaranteed.
// Output writes fully coalesced: warp covers 32 consecutive floats per k.
// ---------------------------------------------------------------------------
__global__ void __launch_bounds__(THREADS, 2)
density_kernel(const float* __restrict__ z,
               const float* __restrict__ z0,
               const float* __restrict__ log_alpha,
               const float* __restrict__ beta,
               const float* __restrict__ mean,
               float* __restrict__ out,
               int N) {
    __shared__ float s_z0[LL][DIM][C];     // [l][d][c] -> conflict-free per-lane c
    __shared__ float s_alpha[LL][C];
    __shared__ float s_beta[LL][C];
    __shared__ float s_mean[DIM][C];
    __shared__ float s_Linv[DIM * DIM][C];
    __shared__ float s_hld[C];
    __shared__ float s_z[PTSB][DIM];       // 64 points

    const int tid = threadIdx.x;
    const int identity = g_identity;       // broadcast LDG, L2-cached

    for (int i = tid; i < LL * C * DIM; i += THREADS) {
        int l = i / (C * DIM);
        int rem = i - l * C * DIM;
        int cc = rem / DIM;
        int d = rem - cc * DIM;
        s_z0[l][d][cc] = z0[i];
    }
    for (int i = tid; i < LL * C; i += THREADS) {
        int l = i / C, cc = i - l * C;
        s_alpha[l][cc] = __expf(log_alpha[i]);
        s_beta[l][cc]  = beta[i];
    }
    for (int i = tid; i < C * DIM; i += THREADS) {
        int cc = i / DIM, d = i - cc * DIM;
        s_mean[d][cc] = mean[i];
    }
    if (!identity) {
        for (int i = tid; i < C * DIM * DIM; i += THREADS) {
            int cc = i / (DIM * DIM);
            int ij = i - cc * DIM * DIM;
            s_Linv[ij][cc] = ((const float*)g_Linv)[i];
        }
    }
    if (tid < C) s_hld[tid] = g_hld[tid];

    // stage 64 points = 1024 floats, coalesced float4 (256 x 16B)
    {
        size_t base_f4 = (size_t)blockIdx.x * (PTSB * DIM / 4);
        size_t nf4 = ((size_t)N * DIM) / 4;
        const float4* zp = (const float4*)z;
        float4 v = make_float4(0.f, 0.f, 0.f, 0.f);
        if (base_f4 + tid < nf4) v = zp[base_f4 + tid];
        ((float4*)&s_z[0][0])[tid] = v;
    }
    __syncthreads();

    const int g = tid >> 4;
    const int c = tid & 15;
    const int nbase = blockIdx.x * PTSB;

    float zc[PPT][DIM];
    #pragma unroll
    for (int k = 0; k < PPT; k++) {
        #pragma unroll
        for (int d = 0; d < DIM; d++) zc[k][d] = s_z[g + GRP * k][d];
    }

    float p1[PPT], p2[PPT];
    #pragma unroll
    for (int k = 0; k < PPT; k++) { p1[k] = 1.0f; p2[k] = 1.0f; }

    #pragma unroll
    for (int l = 0; l < LL; l++) {
        float zl[DIM];
        #pragma unroll
        for (int d = 0; d < DIM; d++) zl[d] = s_z0[l][d][c];
        const float alpha = s_alpha[l][c];
        const float bet   = s_beta[l][c];

        #pragma unroll
        for (int k = 0; k < PPT; k++) {
            float r2 = 0.0f;
            #pragma unroll
            for (int d = 0; d < DIM; d++) {
                float v = zc[k][d] - zl[d];
                r2 = fmaf(v, v, r2);
            }
            float r = sqrtf(r2);
            float h  = __fdividef(1.0f, alpha + r);
            float bh = bet * h;
            float ah = alpha * h;
            #pragma unroll
            for (int d = 0; d < DIM; d++)
                zc[k][d] = fmaf(bh, zc[k][d] - zl[d], zc[k][d]);
            p1[k] = fmaf(p1[k], bh, p1[k]);        // *= (1 + bh)
            p2[k] = fmaf(p2[k], bh * ah, p2[k]);   // *= (1 + bh*ah) == (1 + bh - b*r*h^2)
        }
    }

    float mn[DIM];
    #pragma unroll
    for (int d = 0; d < DIM; d++) mn[d] = s_mean[d][c];
    const float hld = s_hld[c];
    const float NEG_HALF_DIM_LOG2PI = -0.5f * 16.0f * 1.8378770664093453f;

    #pragma unroll
    for (int k = 0; k < PPT; k++) {
        float diff[DIM];
        #pragma unroll
        for (int d = 0; d < DIM; d++) diff[d] = zc[k][d] - mn[d];

        float q = 0.0f;
        if (identity) {
            #pragma unroll
            for (int d = 0; d < DIM; d++) q = fmaf(diff[d], diff[d], q);
        } else {
            #pragma unroll
            for (int i = 0; i < DIM; i++) {
                float s = 0.0f;
                #pragma unroll
                for (int j = 0; j <= i; j++)
                    s = fmaf(s_Linv[i * DIM + j][c], diff[j], s);
                q = fmaf(s, s, q);
            }
        }

        float slj = 15.0f * __logf(p1[k]) + __logf(p2[k]);
        float lp = NEG_HALF_DIM_LOG2PI - 0.5f * q - hld + slj;
        lp = isnan(lp) ? -INFINITY : lp;

        int n = nbase + g + GRP * k;
        if (n < N) out[(size_t)n * C + c] = lp;
    }
}

extern "C" void kernel_launch(void* const* d_in, const int* in_sizes, int n_in,
                              void* d_out, int out_size) {
    const float* z         = (const float*)d_in[0];
    const float* z0        = (const float*)d_in[1];
    const float* log_alpha = (const float*)d_in[2];
    const float* beta      = (const float*)d_in[3];
    const float* mean      = (const float*)d_in[4];
    const float* cov       = (const float*)d_in[5];
    float* out = (float*)d_out;

    const int N = in_sizes[0] / DIM;

    chol_prep_kernel<<<1, THREADS>>>(cov);

    const int blocks = (N + PTSB - 1) / PTSB;
    density_kernel<<<blocks, THREADS>>>(z, z0, log_alpha, beta, mean, out, N);
}